// round 1
// baseline (speedup 1.0000x reference)
#include <cuda_runtime.h>
#include <math.h>

// Problem constants
#define NT 16384   // tokens
#define ND 1024    // model dim
#define NH 2048    // hidden dim
#define NE 8       // experts
#define NA (2*NT)  // total assignments (top-2)

// GEMM tiling
#define BM 128
#define BN 64
#define BK 16
#define BMP (BM+4)   // padded A-tile row stride (keeps 16B alignment, reduces conflicts)

// ---------------- device scratch (no allocation allowed) ----------------
__device__ int   g_counts[NE];
__device__ int   g_cursor[NE];
__device__ int   g_off[NE+1];
__device__ int   g_topi[NT*2];
__device__ float g_topw[NT*2];
__device__ int   g_tok[NA];
__device__ float g_wt[NA];
__device__ float g_h[(size_t)NA * NH];   // 256 MB fp32 hidden activations

// ---------------- packed f32x2 helpers (FFMA2 path) ----------------
__device__ __forceinline__ unsigned long long pk2(float lo, float hi) {
    unsigned long long r;
    asm("mov.b64 %0, {%1, %2};" : "=l"(r) : "f"(lo), "f"(hi));
    return r;
}
__device__ __forceinline__ float2 up2(unsigned long long v) {
    float2 r;
    asm("mov.b64 {%0, %1}, %2;" : "=f"(r.x), "=f"(r.y) : "l"(v));
    return r;
}
__device__ __forceinline__ void fma2(unsigned long long& d,
                                     unsigned long long a,
                                     unsigned long long b) {
    asm("fma.rn.f32x2 %0, %1, %2, %0;" : "+l"(d) : "l"(a), "l"(b));
}

__device__ __forceinline__ float silu_mul(float a, float b) {
    return (a / (1.0f + expf(-a))) * b;
}

// ---------------- kernels ----------------
__global__ void init_kernel() {
    int i = threadIdx.x;
    if (i < NE) g_counts[i] = 0;
}

// One warp per token: logits = x_row @ gate_w, top-2, softmax over the pair.
__global__ void gate_kernel(const float* __restrict__ x,
                            const float* __restrict__ gw) {
    int t    = blockIdx.x * (blockDim.x >> 5) + (threadIdx.x >> 5);
    int lane = threadIdx.x & 31;
    if (t >= NT) return;
    const float* xr = x + (size_t)t * ND;

    float acc[NE];
#pragma unroll
    for (int e = 0; e < NE; e++) acc[e] = 0.f;

    for (int d = lane; d < ND; d += 32) {
        float xv = xr[d];
        const float* g = gw + (size_t)d * NE;
#pragma unroll
        for (int e = 0; e < NE; e++) acc[e] += xv * g[e];
    }
#pragma unroll
    for (int e = 0; e < NE; e++) {
#pragma unroll
        for (int o = 16; o; o >>= 1)
            acc[e] += __shfl_xor_sync(0xffffffffu, acc[e], o);
    }
    if (lane == 0) {
        float v1 = -1e30f, v2 = -1e30f;
        int   i1 = 0, i2 = 0;
#pragma unroll
        for (int e = 0; e < NE; e++) {
            float l = acc[e];
            if (l > v1)      { v2 = v1; i2 = i1; v1 = l; i1 = e; }
            else if (l > v2) { v2 = l;  i2 = e; }
        }
        // softmax over [v1, v2] (v1 is the max)
        float z  = expf(v2 - v1);
        float wa = 1.0f / (1.0f + z);
        float wb = z    / (1.0f + z);
        g_topi[2*t]   = i1;  g_topi[2*t+1] = i2;
        g_topw[2*t]   = wa;  g_topw[2*t+1] = wb;
        atomicAdd(&g_counts[i1], 1);
        atomicAdd(&g_counts[i2], 1);
    }
}

__global__ void offsets_kernel() {
    if (threadIdx.x == 0) {
        int s = 0;
#pragma unroll
        for (int e = 0; e < NE; e++) {
            g_off[e]    = s;
            g_cursor[e] = s;
            s += g_counts[e];
        }
        g_off[NE] = s;
    }
}

__global__ void scatter_kernel() {
    int t = blockIdx.x * blockDim.x + threadIdx.x;
    if (t >= NT) return;
#pragma unroll
    for (int k = 0; k < 2; k++) {
        int e   = g_topi[2*t + k];
        int pos = atomicAdd(&g_cursor[e], 1);
        g_tok[pos] = t;
        g_wt[pos]  = g_topw[2*t + k];
    }
}

// Fused up-projection: for expert e, rows = gathered tokens.
// h = silu(x_g @ w1[e]) * (x_g @ w3[e])  -> g_h
__global__ __launch_bounds__(256)
void up_gemm(const float* __restrict__ x,
             const float* __restrict__ w1,
             const float* __restrict__ w3) {
    __shared__ float As[BK * BMP];
    __shared__ float Bs1[BK * BN];
    __shared__ float Bs3[BK * BN];
    __shared__ int   s_tok[BM];

    int e   = blockIdx.z;
    int cnt = g_counts[e];
    int m0  = blockIdx.y * BM;
    if (m0 >= cnt) return;
    int off = g_off[e];
    int n0  = blockIdx.x * BN;
    int tid = threadIdx.x;

    if (tid < BM) {
        int gr = m0 + tid;
        s_tok[tid] = (gr < cnt) ? g_tok[off + gr] : -1;
    }

    const float* w1b = w1 + (size_t)e * ND * NH;
    const float* w3b = w3 + (size_t)e * ND * NH;

    int ty = tid >> 4;   // 0..15 -> 8 M rows each
    int tx = tid & 15;   // 0..15 -> 4 N cols each

    unsigned long long acc1[8][2], acc3[8][2];
#pragma unroll
    for (int i = 0; i < 8; i++)
#pragma unroll
        for (int j = 0; j < 2; j++) { acc1[i][j] = 0ull; acc3[i][j] = 0ull; }

    __syncthreads();

    for (int k0 = 0; k0 < ND; k0 += BK) {
        // A tile (gathered, transposed into [k][m])
#pragma unroll
        for (int l = 0; l < 2; l++) {
            int f = tid + l * 256;
            int r = f >> 2, c4 = f & 3;
            int tok = s_tok[r];
            float4 v = make_float4(0.f, 0.f, 0.f, 0.f);
            if (tok >= 0)
                v = *(const float4*)(x + (size_t)tok * ND + k0 + c4 * 4);
            As[(c4*4+0)*BMP + r] = v.x;
            As[(c4*4+1)*BMP + r] = v.y;
            As[(c4*4+2)*BMP + r] = v.z;
            As[(c4*4+3)*BMP + r] = v.w;
        }
        // B tiles
        {
            int r = tid >> 4, c = (tid & 15) << 2;
            *(float4*)&Bs1[r*BN + c] = *(const float4*)(w1b + (size_t)(k0+r)*NH + n0 + c);
            *(float4*)&Bs3[r*BN + c] = *(const float4*)(w3b + (size_t)(k0+r)*NH + n0 + c);
        }
        __syncthreads();
#pragma unroll
        for (int kk = 0; kk < BK; kk++) {
            float4 a0 = *(float4*)&As[kk*BMP + ty*8];
            float4 a1 = *(float4*)&As[kk*BMP + ty*8 + 4];
            float4 b1 = *(float4*)&Bs1[kk*BN + tx*4];
            float4 b3 = *(float4*)&Bs3[kk*BN + tx*4];
            unsigned long long bb1[2] = { pk2(b1.x, b1.y), pk2(b1.z, b1.w) };
            unsigned long long bb3[2] = { pk2(b3.x, b3.y), pk2(b3.z, b3.w) };
            float av[8] = {a0.x, a0.y, a0.z, a0.w, a1.x, a1.y, a1.z, a1.w};
#pragma unroll
            for (int i = 0; i < 8; i++) {
                unsigned long long aa = pk2(av[i], av[i]);
                fma2(acc1[i][0], aa, bb1[0]);
                fma2(acc1[i][1], aa, bb1[1]);
                fma2(acc3[i][0], aa, bb3[0]);
                fma2(acc3[i][1], aa, bb3[1]);
            }
        }
        __syncthreads();
    }

    // epilogue: h = silu(acc1) * acc3
#pragma unroll
    for (int i = 0; i < 8; i++) {
        int gr = m0 + ty*8 + i;
        if (gr >= cnt) continue;
        size_t pos = (size_t)(off + gr);
        float* hp = g_h + pos * NH + n0 + tx*4;
        float2 p10 = up2(acc1[i][0]), p11 = up2(acc1[i][1]);
        float2 p30 = up2(acc3[i][0]), p31 = up2(acc3[i][1]);
        hp[0] = silu_mul(p10.x, p30.x);
        hp[1] = silu_mul(p10.y, p30.y);
        hp[2] = silu_mul(p11.x, p31.x);
        hp[3] = silu_mul(p11.y, p31.y);
    }
}

// Down-projection: y = g_h @ w2[e]; out[tok] += wt * y (atomic, 2 adds/elem).
__global__ __launch_bounds__(256)
void down_gemm(const float* __restrict__ w2, float* __restrict__ out) {
    __shared__ float As[BK * BMP];
    __shared__ float Bs[BK * BN];

    int e   = blockIdx.z;
    int cnt = g_counts[e];
    int m0  = blockIdx.y * BM;
    if (m0 >= cnt) return;
    int off = g_off[e];
    int n0  = blockIdx.x * BN;
    int tid = threadIdx.x;
    int ty = tid >> 4, tx = tid & 15;

    const float* w2b = w2 + (size_t)e * NH * ND;

    unsigned long long acc[8][2];
#pragma unroll
    for (int i = 0; i < 8; i++) { acc[i][0] = 0ull; acc[i][1] = 0ull; }

    for (int k0 = 0; k0 < NH; k0 += BK) {
#pragma unroll
        for (int l = 0; l < 2; l++) {
            int f = tid + l * 256;
            int r = f >> 2, c4 = f & 3;
            int gr = m0 + r;
            float4 v = make_float4(0.f, 0.f, 0.f, 0.f);
            if (gr < cnt)
                v = *(const float4*)(g_h + (size_t)(off + gr) * NH + k0 + c4*4);
            As[(c4*4+0)*BMP + r] = v.x;
            As[(c4*4+1)*BMP + r] = v.y;
            As[(c4*4+2)*BMP + r] = v.z;
            As[(c4*4+3)*BMP + r] = v.w;
        }
        {
            int r = tid >> 4, c = (tid & 15) << 2;
            *(float4*)&Bs[r*BN + c] = *(const float4*)(w2b + (size_t)(k0+r)*ND + n0 + c);
        }
        __syncthreads();
#pragma unroll
        for (int kk = 0; kk < BK; kk++) {
            float4 a0 = *(float4*)&As[kk*BMP + ty*8];
            float4 a1 = *(float4*)&As[kk*BMP + ty*8 + 4];
            float4 b  = *(float4*)&Bs[kk*BN + tx*4];
            unsigned long long bb[2] = { pk2(b.x, b.y), pk2(b.z, b.w) };
            float av[8] = {a0.x, a0.y, a0.z, a0.w, a1.x, a1.y, a1.z, a1.w};
#pragma unroll
            for (int i = 0; i < 8; i++) {
                unsigned long long aa = pk2(av[i], av[i]);
                fma2(acc[i][0], aa, bb[0]);
                fma2(acc[i][1], aa, bb[1]);
            }
        }
        __syncthreads();
    }

#pragma unroll
    for (int i = 0; i < 8; i++) {
        int gr = m0 + ty*8 + i;
        if (gr >= cnt) continue;
        int pos  = off + gr;
        int tok  = g_tok[pos];
        float wt = g_wt[pos];
        float* op = out + (size_t)tok * ND + n0 + tx*4;
        float2 p0 = up2(acc[i][0]), p1 = up2(acc[i][1]);
        atomicAdd(op + 0, wt * p0.x);
        atomicAdd(op + 1, wt * p0.y);
        atomicAdd(op + 2, wt * p1.x);
        atomicAdd(op + 3, wt * p1.y);
    }
}

// ---------------- launch ----------------
extern "C" void kernel_launch(void* const* d_in, const int* in_sizes, int n_in,
                              void* d_out, int out_size) {
    const float* x   = (const float*)d_in[0];
    const float* gw  = (const float*)d_in[1];
    const float* w1  = (const float*)d_in[2];
    const float* w3  = (const float*)d_in[3];
    const float* w2  = (const float*)d_in[4];
    float* out = (float*)d_out;
    (void)in_sizes; (void)n_in;

    cudaMemsetAsync(out, 0, (size_t)out_size * sizeof(float));
    init_kernel<<<1, 32>>>();
    gate_kernel<<<NT / 8, 256>>>(x, gw);
    offsets_kernel<<<1, 32>>>();
    scatter_kernel<<<NT / 256, 256>>>();
    up_gemm<<<dim3(NH / BN, NT / BM, NE), 256>>>(x, w1, w3);
    down_gemm<<<dim3(ND / BN, NT / BM, NE), 256>>>(w2, out);
}

// round 2
// speedup vs baseline: 1.0002x; 1.0002x over previous
#include <cuda_runtime.h>
#include <math.h>

// Problem constants
#define NT 16384   // tokens
#define ND 1024    // model dim
#define NH 2048    // hidden dim
#define NE 8       // experts
#define NA (2*NT)  // total assignments (top-2)

// GEMM tiling
#define BM 128
#define BN 64
#define BK 16
#define BMP (BM+4)   // padded A-tile row stride (keeps 16B alignment, reduces conflicts)

// ---------------- device scratch (no allocation allowed) ----------------
__device__ int   g_counts[NE];
__device__ int   g_cursor[NE];
__device__ int   g_off[NE+1];
__device__ int   g_topi[NT*2];
__device__ float g_topw[NT*2];
__device__ int   g_tok[NA];
__device__ float g_wt[NA];
__device__ float g_h[(size_t)NA * NH];   // 256 MB fp32 hidden activations

// ---------------- packed f32x2 helpers (FFMA2 path) ----------------
__device__ __forceinline__ unsigned long long pk2(float lo, float hi) {
    unsigned long long r;
    asm("mov.b64 %0, {%1, %2};" : "=l"(r) : "f"(lo), "f"(hi));
    return r;
}
__device__ __forceinline__ float2 up2(unsigned long long v) {
    float2 r;
    asm("mov.b64 {%0, %1}, %2;" : "=f"(r.x), "=f"(r.y) : "l"(v));
    return r;
}
__device__ __forceinline__ void fma2(unsigned long long& d,
                                     unsigned long long a,
                                     unsigned long long b) {
    asm("fma.rn.f32x2 %0, %1, %2, %0;" : "+l"(d) : "l"(a), "l"(b));
}

__device__ __forceinline__ float silu_mul(float a, float b) {
    return (a / (1.0f + expf(-a))) * b;
}

// ---------------- kernels ----------------
__global__ void init_kernel() {
    int i = threadIdx.x;
    if (i < NE) g_counts[i] = 0;
}

// One warp per token: logits = x_row @ gate_w, top-2, softmax over the pair.
__global__ void gate_kernel(const float* __restrict__ x,
                            const float* __restrict__ gw) {
    int t    = blockIdx.x * (blockDim.x >> 5) + (threadIdx.x >> 5);
    int lane = threadIdx.x & 31;
    if (t >= NT) return;
    const float* xr = x + (size_t)t * ND;

    float acc[NE];
#pragma unroll
    for (int e = 0; e < NE; e++) acc[e] = 0.f;

    for (int d = lane; d < ND; d += 32) {
        float xv = xr[d];
        const float* g = gw + (size_t)d * NE;
#pragma unroll
        for (int e = 0; e < NE; e++) acc[e] += xv * g[e];
    }
#pragma unroll
    for (int e = 0; e < NE; e++) {
#pragma unroll
        for (int o = 16; o; o >>= 1)
            acc[e] += __shfl_xor_sync(0xffffffffu, acc[e], o);
    }
    if (lane == 0) {
        float v1 = -1e30f, v2 = -1e30f;
        int   i1 = 0, i2 = 0;
#pragma unroll
        for (int e = 0; e < NE; e++) {
            float l = acc[e];
            if (l > v1)      { v2 = v1; i2 = i1; v1 = l; i1 = e; }
            else if (l > v2) { v2 = l;  i2 = e; }
        }
        // softmax over [v1, v2] (v1 is the max)
        float z  = expf(v2 - v1);
        float wa = 1.0f / (1.0f + z);
        float wb = z    / (1.0f + z);
        g_topi[2*t]   = i1;  g_topi[2*t+1] = i2;
        g_topw[2*t]   = wa;  g_topw[2*t+1] = wb;
        atomicAdd(&g_counts[i1], 1);
        atomicAdd(&g_counts[i2], 1);
    }
}

__global__ void offsets_kernel() {
    if (threadIdx.x == 0) {
        int s = 0;
#pragma unroll
        for (int e = 0; e < NE; e++) {
            g_off[e]    = s;
            g_cursor[e] = s;
            s += g_counts[e];
        }
        g_off[NE] = s;
    }
}

__global__ void scatter_kernel() {
    int t = blockIdx.x * blockDim.x + threadIdx.x;
    if (t >= NT) return;
#pragma unroll
    for (int k = 0; k < 2; k++) {
        int e   = g_topi[2*t + k];
        int pos = atomicAdd(&g_cursor[e], 1);
        g_tok[pos] = t;
        g_wt[pos]  = g_topw[2*t + k];
    }
}

// Fused up-projection: for expert e, rows = gathered tokens.
// h = silu(x_g @ w1[e]) * (x_g @ w3[e])  -> g_h
__global__ __launch_bounds__(256)
void up_gemm(const float* __restrict__ x,
             const float* __restrict__ w1,
             const float* __restrict__ w3) {
    __shared__ float As[BK * BMP];
    __shared__ float Bs1[BK * BN];
    __shared__ float Bs3[BK * BN];
    __shared__ int   s_tok[BM];

    int e   = blockIdx.z;
    int cnt = g_counts[e];
    int m0  = blockIdx.y * BM;
    if (m0 >= cnt) return;
    int off = g_off[e];
    int n0  = blockIdx.x * BN;
    int tid = threadIdx.x;

    if (tid < BM) {
        int gr = m0 + tid;
        s_tok[tid] = (gr < cnt) ? g_tok[off + gr] : -1;
    }

    const float* w1b = w1 + (size_t)e * ND * NH;
    const float* w3b = w3 + (size_t)e * ND * NH;

    int ty = tid >> 4;   // 0..15 -> 8 M rows each
    int tx = tid & 15;   // 0..15 -> 4 N cols each

    unsigned long long acc1[8][2], acc3[8][2];
#pragma unroll
    for (int i = 0; i < 8; i++)
#pragma unroll
        for (int j = 0; j < 2; j++) { acc1[i][j] = 0ull; acc3[i][j] = 0ull; }

    __syncthreads();

    for (int k0 = 0; k0 < ND; k0 += BK) {
        // A tile (gathered, transposed into [k][m])
#pragma unroll
        for (int l = 0; l < 2; l++) {
            int f = tid + l * 256;
            int r = f >> 2, c4 = f & 3;
            int tok = s_tok[r];
            float4 v = make_float4(0.f, 0.f, 0.f, 0.f);
            if (tok >= 0)
                v = *(const float4*)(x + (size_t)tok * ND + k0 + c4 * 4);
            As[(c4*4+0)*BMP + r] = v.x;
            As[(c4*4+1)*BMP + r] = v.y;
            As[(c4*4+2)*BMP + r] = v.z;
            As[(c4*4+3)*BMP + r] = v.w;
        }
        // B tiles
        {
            int r = tid >> 4, c = (tid & 15) << 2;
            *(float4*)&Bs1[r*BN + c] = *(const float4*)(w1b + (size_t)(k0+r)*NH + n0 + c);
            *(float4*)&Bs3[r*BN + c] = *(const float4*)(w3b + (size_t)(k0+r)*NH + n0 + c);
        }
        __syncthreads();
#pragma unroll
        for (int kk = 0; kk < BK; kk++) {
            float4 a0 = *(float4*)&As[kk*BMP + ty*8];
            float4 a1 = *(float4*)&As[kk*BMP + ty*8 + 4];
            float4 b1 = *(float4*)&Bs1[kk*BN + tx*4];
            float4 b3 = *(float4*)&Bs3[kk*BN + tx*4];
            unsigned long long bb1[2] = { pk2(b1.x, b1.y), pk2(b1.z, b1.w) };
            unsigned long long bb3[2] = { pk2(b3.x, b3.y), pk2(b3.z, b3.w) };
            float av[8] = {a0.x, a0.y, a0.z, a0.w, a1.x, a1.y, a1.z, a1.w};
#pragma unroll
            for (int i = 0; i < 8; i++) {
                unsigned long long aa = pk2(av[i], av[i]);
                fma2(acc1[i][0], aa, bb1[0]);
                fma2(acc1[i][1], aa, bb1[1]);
                fma2(acc3[i][0], aa, bb3[0]);
                fma2(acc3[i][1], aa, bb3[1]);
            }
        }
        __syncthreads();
    }

    // epilogue: h = silu(acc1) * acc3
#pragma unroll
    for (int i = 0; i < 8; i++) {
        int gr = m0 + ty*8 + i;
        if (gr >= cnt) continue;
        size_t pos = (size_t)(off + gr);
        float* hp = g_h + pos * NH + n0 + tx*4;
        float2 p10 = up2(acc1[i][0]), p11 = up2(acc1[i][1]);
        float2 p30 = up2(acc3[i][0]), p31 = up2(acc3[i][1]);
        hp[0] = silu_mul(p10.x, p30.x);
        hp[1] = silu_mul(p10.y, p30.y);
        hp[2] = silu_mul(p11.x, p31.x);
        hp[3] = silu_mul(p11.y, p31.y);
    }
}

// Down-projection: y = g_h @ w2[e]; out[tok] += wt * y (atomic, 2 adds/elem).
__global__ __launch_bounds__(256)
void down_gemm(const float* __restrict__ w2, float* __restrict__ out) {
    __shared__ float As[BK * BMP];
    __shared__ float Bs[BK * BN];

    int e   = blockIdx.z;
    int cnt = g_counts[e];
    int m0  = blockIdx.y * BM;
    if (m0 >= cnt) return;
    int off = g_off[e];
    int n0  = blockIdx.x * BN;
    int tid = threadIdx.x;
    int ty = tid >> 4, tx = tid & 15;

    const float* w2b = w2 + (size_t)e * NH * ND;

    unsigned long long acc[8][2];
#pragma unroll
    for (int i = 0; i < 8; i++) { acc[i][0] = 0ull; acc[i][1] = 0ull; }

    for (int k0 = 0; k0 < NH; k0 += BK) {
#pragma unroll
        for (int l = 0; l < 2; l++) {
            int f = tid + l * 256;
            int r = f >> 2, c4 = f & 3;
            int gr = m0 + r;
            float4 v = make_float4(0.f, 0.f, 0.f, 0.f);
            if (gr < cnt)
                v = *(const float4*)(g_h + (size_t)(off + gr) * NH + k0 + c4*4);
            As[(c4*4+0)*BMP + r] = v.x;
            As[(c4*4+1)*BMP + r] = v.y;
            As[(c4*4+2)*BMP + r] = v.z;
            As[(c4*4+3)*BMP + r] = v.w;
        }
        {
            int r = tid >> 4, c = (tid & 15) << 2;
            *(float4*)&Bs[r*BN + c] = *(const float4*)(w2b + (size_t)(k0+r)*ND + n0 + c);
        }
        __syncthreads();
#pragma unroll
        for (int kk = 0; kk < BK; kk++) {
            float4 a0 = *(float4*)&As[kk*BMP + ty*8];
            float4 a1 = *(float4*)&As[kk*BMP + ty*8 + 4];
            float4 b  = *(float4*)&Bs[kk*BN + tx*4];
            unsigned long long bb[2] = { pk2(b.x, b.y), pk2(b.z, b.w) };
            float av[8] = {a0.x, a0.y, a0.z, a0.w, a1.x, a1.y, a1.z, a1.w};
#pragma unroll
            for (int i = 0; i < 8; i++) {
                unsigned long long aa = pk2(av[i], av[i]);
                fma2(acc[i][0], aa, bb[0]);
                fma2(acc[i][1], aa, bb[1]);
            }
        }
        __syncthreads();
    }

#pragma unroll
    for (int i = 0; i < 8; i++) {
        int gr = m0 + ty*8 + i;
        if (gr >= cnt) continue;
        int pos  = off + gr;
        int tok  = g_tok[pos];
        float wt = g_wt[pos];
        float* op = out + (size_t)tok * ND + n0 + tx*4;
        float2 p0 = up2(acc[i][0]), p1 = up2(acc[i][1]);
        atomicAdd(op + 0, wt * p0.x);
        atomicAdd(op + 1, wt * p0.y);
        atomicAdd(op + 2, wt * p1.x);
        atomicAdd(op + 3, wt * p1.y);
    }
}

// ---------------- launch ----------------
extern "C" void kernel_launch(void* const* d_in, const int* in_sizes, int n_in,
                              void* d_out, int out_size) {
    const float* x   = (const float*)d_in[0];
    const float* gw  = (const float*)d_in[1];
    const float* w1  = (const float*)d_in[2];
    const float* w3  = (const float*)d_in[3];
    const float* w2  = (const float*)d_in[4];
    float* out = (float*)d_out;
    (void)in_sizes; (void)n_in;

    cudaMemsetAsync(out, 0, (size_t)out_size * sizeof(float));
    init_kernel<<<1, 32>>>();
    gate_kernel<<<NT / 8, 256>>>(x, gw);
    offsets_kernel<<<1, 32>>>();
    scatter_kernel<<<NT / 256, 256>>>();
    up_gemm<<<dim3(NH / BN, NT / BM, NE), 256>>>(x, w1, w3);
    down_gemm<<<dim3(ND / BN, NT / BM, NE), 256>>>(w2, out);
}